// round 9
// baseline (speedup 1.0000x reference)
#include <cuda_runtime.h>
#include <cuda_bf16.h>
#include <cstdint>
#include <cstddef>
#include <math.h>

// ---------------------------------------------------------------------------
// Problem constants
// ---------------------------------------------------------------------------
#define BB   8       // batch
#define NF   4096    // N_FULL
#define NL   1024    // N_LAT
#define CC   256     // channels
#define HH   8       // heads
#define VD   32      // C / H

// ---------------------------------------------------------------------------
// Scratch layout (single __device__ array; no allocations allowed)
// ---------------------------------------------------------------------------
static const size_t OFF_ATT     = 0;
static const size_t OFF_ATT_P   = OFF_ATT     + (size_t)HH*NL*NF;
static const size_t OFF_VAL     = OFF_ATT_P   + (size_t)HH*NL*NL;
static const size_t OFF_HFULL   = OFF_VAL     + (size_t)BB*NF*CC;
static const size_t OFF_TMPFULL = OFF_HFULL   + (size_t)BB*NF*CC;
static const size_t OFF_LAT0    = OFF_TMPFULL + (size_t)BB*NF*CC;
static const size_t OFF_LAT1    = OFF_LAT0    + (size_t)BB*NL*CC;
static const size_t OFF_LAT2    = OFF_LAT1    + (size_t)BB*NL*CC;
static const size_t OFF_WREP    = OFF_LAT2    + (size_t)BB*NL*CC;
static const size_t SCRATCH_ELEMS = OFF_WREP + (size_t)CC*CC;

__device__ float g_scratch[SCRATCH_ELEMS];

// ---------------------------------------------------------------------------
// Device helpers
// ---------------------------------------------------------------------------
__device__ __forceinline__ float gelu_tanh(float x) {
    const float k0 = 0.7978845608028654f;
    const float k1 = 0.044715f;
    float x3 = x * x * x;
    float t  = tanhf(k0 * (x + k1 * x3));
    return 0.5f * x * (1.0f + t);
}

__device__ __forceinline__ float head_scale(float rv) {
    const float c = (float)(0.25 * 3.14159265358979323846 * (1.0 - 1e-7));
    float s = sinf(rv);
    return tanf(c * (1.0f + s));
}

// Split (x, y) into bf16 hi pair + bf16 lo pair (lo = exact residual, bf16-rounded)
__device__ __forceinline__ void bfsplit2(float x, float y, uint32_t& hi, uint32_t& lo) {
    __nv_bfloat162 h = __floats2bfloat162_rn(x, y);
    float2 hf = __bfloat1622float2(h);
    __nv_bfloat162 l = __floats2bfloat162_rn(x - hf.x, y - hf.y);
    hi = *(uint32_t*)&h;
    lo = *(uint32_t*)&l;
}

__device__ __forceinline__ void mma_bf16(float* d, const uint32_t* a, const uint32_t* b) {
    asm volatile(
        "mma.sync.aligned.m16n8k16.row.col.f32.bf16.bf16.f32 "
        "{%0,%1,%2,%3}, {%4,%5,%6,%7}, {%8,%9}, {%0,%1,%2,%3};"
        : "+f"(d[0]), "+f"(d[1]), "+f"(d[2]), "+f"(d[3])
        : "r"(a[0]), "r"(a[1]), "r"(a[2]), "r"(a[3]), "r"(b[0]), "r"(b[1]));
}

// ---------------------------------------------------------------------------
// Encoder: h[b,n,c] = gelu(sum_{j<4} x[b,n,j]*W[j,c] + b[c])
// ---------------------------------------------------------------------------
__global__ void k_encoder(const float* __restrict__ x,
                          const float* __restrict__ w,
                          const float* __restrict__ bias,
                          float* __restrict__ out) {
    int idx = blockIdx.x * blockDim.x + threadIdx.x;   // total = B*NF*CC
    int m = idx >> 8;
    int c = idx & 255;
    const float* xr = x + (size_t)m * 4;
    float acc = bias[c];
    acc += xr[0] * w[c] + xr[1] * w[256 + c] + xr[2] * w[512 + c] + xr[3] * w[768 + c];
    out[idx] = gelu_tanh(acc);
}

// ---------------------------------------------------------------------------
// Repack head weights [H, C, VD] -> [C, H*VD] row-major
// ---------------------------------------------------------------------------
__global__ void k_repack_w(const float* __restrict__ w_hcv, float* __restrict__ wrep) {
    int idx = blockIdx.x * blockDim.x + threadIdx.x;   // 65536
    int k = idx >> 8;
    int n = idx & 255;
    int h = n >> 5;
    int v = n & 31;
    wrep[idx] = w_hcv[(size_t)h * CC * VD + (size_t)k * VD + v];
}

// ---------------------------------------------------------------------------
// Global (unmasked) attention rows: att = softmax(-md*scale) per (h,q) row.
// ---------------------------------------------------------------------------
__global__ void k_att_global(const float* __restrict__ md,
                             const float* __restrict__ r,
                             float* __restrict__ att,
                             int Nq, int Nk) {
    extern __shared__ float sm[];
    float* row = sm;
    float* red = sm + Nk;
    int rowid = blockIdx.x;
    int h = rowid / Nq;
    float scale = head_scale(r[h]);
    const float* src = md + (size_t)rowid * Nk;
    float* dst = att + (size_t)rowid * Nk;
    int tid = threadIdx.x;

    float mn = 3.402823466e+38f;
    for (int k = tid; k < Nk; k += 256) {
        float v = src[k] * scale;
        row[k] = v;
        mn = fminf(mn, v);
    }
    red[tid] = mn; __syncthreads();
    for (int s = 128; s > 0; s >>= 1) {
        if (tid < s) red[tid] = fminf(red[tid], red[tid + s]);
        __syncthreads();
    }
    mn = red[0];
    __syncthreads();

    float sum = 0.0f;
    for (int k = tid; k < Nk; k += 256) {
        float e = expf(mn - row[k]);   // logits = -sd; max logit = -mn
        row[k] = e;
        sum += e;
    }
    red[tid] = sum; __syncthreads();
    for (int s = 128; s > 0; s >>= 1) {
        if (tid < s) red[tid] += red[tid + s];
        __syncthreads();
    }
    float inv = 1.0f / red[0];
    for (int k = tid; k < Nk; k += 256) dst[k] = row[k] * inv;
}

// ---------------------------------------------------------------------------
// Masked attention rows (locality=30, Nk=1024)
// ---------------------------------------------------------------------------
__global__ void k_att_masked(const float* __restrict__ md,
                             const float* __restrict__ r,
                             float* __restrict__ att) {
    __shared__ float vals[NL];
    __shared__ float srt[NL];
    __shared__ float red[256];
    int rowid = blockIdx.x;           // h*NL + q
    int h = rowid / NL;
    float scale = head_scale(r[h]);
    const float* src = md + (size_t)rowid * NL;
    float* dst = att + (size_t)rowid * NL;
    int tid = threadIdx.x;

    for (int k = tid; k < NL; k += 256) {
        float v = src[k] * scale;
        vals[k] = v;
        srt[k]  = v;
    }
    __syncthreads();

    // Bitonic sort ascending (1024 elements)
    for (int k = 2; k <= NL; k <<= 1) {
        for (int j = k >> 1; j > 0; j >>= 1) {
            for (int i = tid; i < NL; i += 256) {
                int ixj = i ^ j;
                if (ixj > i) {
                    bool up = ((i & k) == 0);
                    float a = srt[i], b = srt[ixj];
                    if ((a > b) == up) { srt[i] = b; srt[ixj] = a; }
                }
            }
            __syncthreads();
        }
    }

    // percentile(30) over n=1024: idx = 0.3*1023 = 306.9
    float a306 = srt[306], a307 = srt[307];
    float thr = a306 + 0.9f * (a307 - a306);
    float mn  = srt[0];

    float sum = 0.0f;
    for (int k = tid; k < NL; k += 256) {
        float v = vals[k];
        float e = (v <= thr) ? expf(mn - v) : 0.0f;
        vals[k] = e;
        sum += e;
    }
    red[tid] = sum; __syncthreads();
    for (int s = 128; s > 0; s >>= 1) {
        if (tid < s) red[tid] += red[tid + s];
        __syncthreads();
    }
    float inv = 1.0f / red[0];
    for (int k = tid; k < NL; k += 256) dst[k] = vals[k] * inv;
}

// ---------------------------------------------------------------------------
// Split-bf16 tensor-core GEMM: C = epilogue(A[M,K] @ B[K,256]).
// Block tile 64x64x16, 128 threads, 4 warps (2 along M x 2 along N).
// Warp tile 32x32 via m16n8k16 (2x4 MMA tiles), 3-term split precision:
//   A = Ah + Al, B = Bh + Bl (bf16 each); D += Ah*Bh + Ah*Bl + Al*Bh.
// Double-buffered smem with fragments pre-arranged in MMA lane order.
//   grid: (M/64, 4, nHeads); blockIdx.z offsets A/B by per-head strides.
//   flags: bit0 = gelu, bit1 = add addbuf[m*256+n]
//   store_mode: 0 plain; 1 att-apply scatter; 2 value scatter.
// Requires M%64==0, K%16==0 (true at all call sites).
//
// m16n8k16 bf16 fragment maps (PTX ISA):
//   A 16x16: k-pair c=k>>1: lane=(r&7)*4+(c&3), reg=(r>>3)+2*(c>>2)
//   B 16x8 : k-pair t=k>>1: lane=n*4+(t&3),     reg=t>>2
//   C 16x8 : c0/c1 at (lane>>2, (lane&3)*2 +0/1), c2/c3 at row +8
// ---------------------------------------------------------------------------
__global__ void __launch_bounds__(128)
k_gemm_bf(const float* __restrict__ A, const float* __restrict__ B,
          float* __restrict__ C, int M, int K,
          size_t strideA_h, size_t strideB_h,
          const float* __restrict__ bias, const float* __restrict__ addbuf,
          int flags, int store_mode, int s_param)
{
    const int h = blockIdx.z;
    A += (size_t)h * strideA_h;
    B += (size_t)h * strideB_h;

    // A planes: [buf][mtile(4)][lane*4 + reg]   (128 words per 16x16 tile)
    // B planes: [buf][ntile(8)][lane*2 + reg]   (64 words + pad 2)
    __shared__ uint32_t AsH[2][4][128];
    __shared__ uint32_t AsL[2][4][128];
    __shared__ uint32_t BsH[2][8][66];
    __shared__ uint32_t BsL[2][8][66];

    const int tid  = threadIdx.x;
    const int lane = tid & 31;
    const int warp = tid >> 5;
    const int wm   = warp & 1;       // 0..1  (M)
    const int wn   = warp >> 1;      // 0..1  (N)
    const int m0   = blockIdx.x * 64;
    const int n0   = blockIdx.y * 64;

    float acc[2][4][4];
#pragma unroll
    for (int mi = 0; mi < 2; mi++)
#pragma unroll
        for (int ni = 0; ni < 4; ni++)
#pragma unroll
            for (int q = 0; q < 4; q++) acc[mi][ni][q] = 0.0f;

    float4 ra[2];
    float2 rb0[2], rb1[2];
    const int KT = K >> 4;

    auto FETCH = [&](int kt) {
        int k0 = kt * 16;
        // A tile 64x16: 256 float4 slots, 2 per thread
#pragma unroll
        for (int p = 0; p < 2; p++) {
            int id = tid + p * 128;           // 0..255
            int m = id >> 2, kq = id & 3;     // row / float4-of-k
            ra[p] = *(const float4*)(A + (size_t)(m0 + m) * K + k0 + kq * 4);
        }
        // B tile 16x64: per slot, float2 along n from rows k and k+1
#pragma unroll
        for (int p = 0; p < 2; p++) {
            int id = tid + p * 128;           // 0..255
            int n2 = id & 31, k8 = id >> 5;   // n-pair index / k-pair row
            const float* bp = B + (size_t)(k0 + k8 * 2) * 256 + n0 + n2 * 2;
            rb0[p] = *(const float2*)bp;          // row k
            rb1[p] = *(const float2*)(bp + 256);  // row k+1
        }
    };

    auto STORE = [&](int buf) {
#pragma unroll
        for (int p = 0; p < 2; p++) {
            int id = tid + p * 128;
            int m = id >> 2, kq = id & 3;
            int r = m & 15, mt = m >> 4;
            // k-pairs c0 = kq*2 (f.x,f.y) and c0+1 (f.z,f.w)
            int c0 = kq * 2;
            uint32_t hi0, lo0, hi1, lo1;
            bfsplit2(ra[p].x, ra[p].y, hi0, lo0);
            bfsplit2(ra[p].z, ra[p].w, hi1, lo1);
            int reg = (r >> 3) + 2 * (c0 >> 2);        // same for c0, c0+1
            int l0 = (r & 7) * 4 + (c0 & 3);
            AsH[buf][mt][l0 * 4 + reg]       = hi0;
            AsH[buf][mt][(l0 + 1) * 4 + reg] = hi1;
            AsL[buf][mt][l0 * 4 + reg]       = lo0;
            AsL[buf][mt][(l0 + 1) * 4 + reg] = lo1;
        }
#pragma unroll
        for (int p = 0; p < 2; p++) {
            int id = tid + p * 128;
            int n2 = id & 31, k8 = id >> 5;   // t = k8
            int nt = n2 >> 2;
            int reg = k8 >> 2;
            // n = n2*2 + e: word = k-pair (row k, row k+1) at column n
            uint32_t hiA, loA, hiB, loB;
            bfsplit2(rb0[p].x, rb1[p].x, hiA, loA);   // column n2*2
            bfsplit2(rb0[p].y, rb1[p].y, hiB, loB);   // column n2*2+1
            int nn = (n2 * 2) & 7;
            int lA = nn * 4 + (k8 & 3);
            int lB = (nn + 1) * 4 + (k8 & 3);
            BsH[buf][nt][lA * 2 + reg] = hiA;
            BsH[buf][nt][lB * 2 + reg] = hiB;
            BsL[buf][nt][lA * 2 + reg] = loA;
            BsL[buf][nt][lB * 2 + reg] = loB;
        }
    };

    auto COMPUTE = [&](int buf) {
        uint32_t afH[2][4], afL[2][4];
        uint32_t bfH[4][2], bfL[4][2];
#pragma unroll
        for (int mi = 0; mi < 2; mi++) {
            uint4 th = *(const uint4*)&AsH[buf][wm * 2 + mi][lane * 4];
            afH[mi][0] = th.x; afH[mi][1] = th.y; afH[mi][2] = th.z; afH[mi][3] = th.w;
            uint4 tl = *(const uint4*)&AsL[buf][wm * 2 + mi][lane * 4];
            afL[mi][0] = tl.x; afL[mi][1] = tl.y; afL[mi][2] = tl.z; afL[mi][3] = tl.w;
        }
#pragma unroll
        for (int ni = 0; ni < 4; ni++) {
            uint2 th = *(const uint2*)&BsH[buf][wn * 4 + ni][lane * 2];
            bfH[ni][0] = th.x; bfH[ni][1] = th.y;
            uint2 tl = *(const uint2*)&BsL[buf][wn * 4 + ni][lane * 2];
            bfL[ni][0] = tl.x; bfL[ni][1] = tl.y;
        }
#pragma unroll
        for (int mi = 0; mi < 2; mi++)
#pragma unroll
            for (int ni = 0; ni < 4; ni++) {
                mma_bf16(acc[mi][ni], afH[mi], bfH[ni]);
                mma_bf16(acc[mi][ni], afH[mi], bfL[ni]);
                mma_bf16(acc[mi][ni], afL[mi], bfH[ni]);
            }
    };

    FETCH(0);
    STORE(0);
    for (int kt = 0; kt < KT; kt++) {
        __syncthreads();
        int buf = kt & 1;
        if (kt + 1 < KT) FETCH(kt + 1);
        COMPUTE(buf);
        if (kt + 1 < KT) STORE(buf ^ 1);
    }

    // ---- epilogue ----
    const int gr = lane >> 2;
    const int gc = lane & 3;
#pragma unroll
    for (int mi = 0; mi < 2; mi++) {
#pragma unroll
        for (int hf = 0; hf < 2; hf++) {
            int m = m0 + wm * 32 + mi * 16 + gr + hf * 8;
#pragma unroll
            for (int ni = 0; ni < 4; ni++) {
                int n = n0 + wn * 32 + ni * 8 + gc * 2;
                float v0 = acc[mi][ni][hf * 2 + 0];
                float v1 = acc[mi][ni][hf * 2 + 1];
                if (bias) { v0 += bias[n]; v1 += bias[n + 1]; }
                if (flags & 2) {
                    v0 += addbuf[(size_t)m * 256 + n];
                    v1 += addbuf[(size_t)m * 256 + n + 1];
                }
                if (flags & 1) { v0 = gelu_tanh(v0); v1 = gelu_tanh(v1); }
                size_t idx;
                if (store_mode == 0) {
                    idx = (size_t)m * 256 + n;
                } else if (store_mode == 1) {
                    int bb = n >> 5, vv = n & 31;
                    idx = (size_t)bb * s_param * 256 + (size_t)m * 256 + (size_t)h * 32 + vv;
                } else {
                    int bb = m / s_param, kp = m % s_param;
                    int hh = n >> 5, vv = n & 31;
                    idx = (size_t)hh * s_param * 256 + (size_t)kp * 256 + (size_t)bb * 32 + vv;
                }
                *(float2*)(C + idx) = make_float2(v0, v1);
            }
        }
    }
}

// ---------------------------------------------------------------------------
// Final projection: out[m] = A[m,:] . w[:,0] + b[0]   (one warp per row)
// ---------------------------------------------------------------------------
__global__ void k_fc2(const float* __restrict__ A, const float* __restrict__ w,
                      const float* __restrict__ b, float* __restrict__ out, int M) {
    int gwarp = (blockIdx.x * blockDim.x + threadIdx.x) >> 5;
    int lane = threadIdx.x & 31;
    if (gwarp >= M) return;
    const float* a = A + (size_t)gwarp * 256;
    float s = 0.0f;
#pragma unroll
    for (int k = lane; k < 256; k += 32) s += a[k] * w[k];
#pragma unroll
    for (int off = 16; off > 0; off >>= 1)
        s += __shfl_down_sync(0xFFFFFFFFu, s, off);
    if (lane == 0) out[gwarp] = s + b[0];
}

// ---------------------------------------------------------------------------
// Host orchestration
// ---------------------------------------------------------------------------
extern "C" void kernel_launch(void* const* d_in, const int* in_sizes, int n_in,
                              void* d_out, int out_size) {
    (void)in_sizes; (void)n_in; (void)out_size;

    const float* x       = (const float*)d_in[0];
    const float* md_down = (const float*)d_in[1];
    const float* md_p[2] = {(const float*)d_in[2], (const float*)d_in[3]};
    const float* md_up   = (const float*)d_in[4];
    const float* en_w    = (const float*)d_in[5];
    const float* en_b    = (const float*)d_in[6];
    const float* down_r  = (const float*)d_in[7];
    const float* down_w  = (const float*)d_in[8];
    const float* pa_r[2] = {(const float*)d_in[9],  (const float*)d_in[17]};
    const float* pa_w[2] = {(const float*)d_in[10], (const float*)d_in[18]};
    const float* f1w[2]  = {(const float*)d_in[11], (const float*)d_in[19]};
    const float* f1b[2]  = {(const float*)d_in[12], (const float*)d_in[20]};
    const float* f2w[2]  = {(const float*)d_in[13], (const float*)d_in[21]};
    const float* f2b[2]  = {(const float*)d_in[14], (const float*)d_in[22]};
    const float* rw[2]   = {(const float*)d_in[15], (const float*)d_in[23]};
    const float* rb[2]   = {(const float*)d_in[16], (const float*)d_in[24]};
    const float* up_r    = (const float*)d_in[25];
    const float* up_w    = (const float*)d_in[26];
    const float* de1w    = (const float*)d_in[27];
    const float* de1b    = (const float*)d_in[28];
    const float* de2w    = (const float*)d_in[29];
    const float* de2b    = (const float*)d_in[30];

    float* S = nullptr;
    cudaGetSymbolAddress((void**)&S, g_scratch);
    float* att     = S + OFF_ATT;
    float* attp    = S + OFF_ATT_P;
    float* val     = S + OFF_VAL;
    float* hfull   = S + OFF_HFULL;
    float* tmpfull = S + OFF_TMPFULL;
    float* lat0    = S + OFF_LAT0;
    float* lat1    = S + OFF_LAT1;
    float* lat2    = S + OFF_LAT2;
    float* wrep    = S + OFF_WREP;

    // ---- encoder ----
    k_encoder<<<(BB * NF * CC) / 256, 256>>>(x, en_w, en_b, hfull);

    // ---- down attention (global, Nq=1024, Nk=4096) ----
    k_repack_w<<<256, 256>>>(down_w, wrep);
    k_gemm_bf<<<dim3(BB * NF / 64, 4, 1), 128>>>(
        hfull, wrep, val, BB * NF, 256, 0, 0, nullptr, nullptr, 0, 2, NF);
    k_att_global<<<HH * NL, 256, (NF + 256) * sizeof(float)>>>(md_down, down_r, att, NL, NF);
    k_gemm_bf<<<dim3(NL / 64, 4, HH), 128>>>(
        att, val, lat0, NL, NF, (size_t)NL * NF, (size_t)NF * CC,
        nullptr, nullptr, 1, 1, NL);

    // ---- two latent PiT blocks (masked attention, locality=30) ----
    float* hin  = lat0;
    float* bufP = lat1;
    float* bufT = lat2;
    for (int i = 0; i < 2; i++) {
        k_repack_w<<<256, 256>>>(pa_w[i], wrep);
        k_gemm_bf<<<dim3(BB * NL / 64, 4, 1), 128>>>(
            hin, wrep, val, BB * NL, 256, 0, 0, nullptr, nullptr, 0, 2, NL);
        k_att_masked<<<HH * NL, 256>>>(md_p[i], pa_r[i], attp);
        k_gemm_bf<<<dim3(NL / 64, 4, HH), 128>>>(
            attp, val, bufP, NL, NL, (size_t)NL * NL, (size_t)NL * CC,
            nullptr, nullptr, 1, 1, NL);
        // mlp fc1 (gelu)
        k_gemm_bf<<<dim3(BB * NL / 64, 4, 1), 128>>>(
            bufP, f1w[i], bufT, BB * NL, 256, 0, 0, f1b[i], nullptr, 1, 0, 0);
        // mlp fc2 (no act) -> overwrite bufP
        k_gemm_bf<<<dim3(BB * NL / 64, 4, 1), 128>>>(
            bufT, f2w[i], bufP, BB * NL, 256, 0, 0, f2b[i], nullptr, 0, 0, 0);
        // h = gelu(mlp + hin@rw + rb) -> bufT
        k_gemm_bf<<<dim3(BB * NL / 64, 4, 1), 128>>>(
            hin, rw[i], bufT, BB * NL, 256, 0, 0, rb[i], bufP, 3, 0, 0);
        float* nh = bufT; bufT = hin; hin = nh;
    }

    // ---- up attention (global, Nq=4096, Nk=1024) ----
    k_repack_w<<<256, 256>>>(up_w, wrep);
    k_gemm_bf<<<dim3(BB * NL / 64, 4, 1), 128>>>(
        hin, wrep, val, BB * NL, 256, 0, 0, nullptr, nullptr, 0, 2, NL);
    k_att_global<<<HH * NF, 256, (NL + 256) * sizeof(float)>>>(md_up, up_r, att, NF, NL);
    k_gemm_bf<<<dim3(NF / 64, 4, HH), 128>>>(
        att, val, hfull, NF, NL, (size_t)NF * NL, (size_t)NL * CC,
        nullptr, nullptr, 1, 1, NF);

    // ---- decoder ----
    k_gemm_bf<<<dim3(BB * NF / 64, 4, 1), 128>>>(
        hfull, de1w, tmpfull, BB * NF, 256, 0, 0, de1b, nullptr, 1, 0, 0);
    k_fc2<<<(BB * NF * 32) / 256, 256>>>(tmpfull, de2w, de2b, (float*)d_out, BB * NF);
}

// round 13
// speedup vs baseline: 1.0746x; 1.0746x over previous
#include <cuda_runtime.h>
#include <cuda_bf16.h>
#include <cstdint>
#include <cstddef>
#include <math.h>

// ---------------------------------------------------------------------------
// Problem constants
// ---------------------------------------------------------------------------
#define BB   8       // batch
#define NF   4096    // N_FULL
#define NL   1024    // N_LAT
#define CC   256     // channels
#define HH   8       // heads
#define VD   32      // C / H

// ---------------------------------------------------------------------------
// Scratch: all tensors stored as separate bf16 hi / lo planes.
// Offsets in 4-byte words within g_scratch.
// ---------------------------------------------------------------------------
static const size_t W_ATT  = (size_t)HH * NL * NF / 2;   // 16,777,216 words per plane
static const size_t W_ATTP = (size_t)HH * NL * NL / 2;   //  4,194,304
static const size_t W_BIG  = (size_t)BB * NF * CC / 2;   //  4,194,304
static const size_t W_LAT  = (size_t)BB * NL * CC / 2;   //  1,048,576
static const size_t W_WT   = (size_t)CC * CC / 2;        //     32,768

static const size_t OFF_ATT_H  = 0;
static const size_t OFF_ATT_L  = OFF_ATT_H  + W_ATT;
static const size_t OFF_ATTP_H = OFF_ATT_L  + W_ATT;
static const size_t OFF_ATTP_L = OFF_ATTP_H + W_ATTP;
static const size_t OFF_VAL_H  = OFF_ATTP_L + W_ATTP;
static const size_t OFF_VAL_L  = OFF_VAL_H  + W_BIG;
static const size_t OFF_VALT_H = OFF_VAL_L  + W_BIG;
static const size_t OFF_VALT_L = OFF_VALT_H + W_BIG;
static const size_t OFF_HF_H   = OFF_VALT_L + W_BIG;
static const size_t OFF_HF_L   = OFF_HF_H   + W_BIG;
static const size_t OFF_TMP_H  = OFF_HF_L   + W_BIG;
static const size_t OFF_TMP_L  = OFF_TMP_H  + W_BIG;
static const size_t OFF_LAT    = OFF_TMP_L  + W_BIG;     // 6 planes: lat0H,lat0L,lat1H,lat1L,lat2H,lat2L
static const size_t OFF_WT_H   = OFF_LAT    + 6 * W_LAT;
static const size_t OFF_WT_L   = OFF_WT_H   + W_WT;
static const size_t SCRATCH_ELEMS = OFF_WT_L + W_WT;

__device__ float g_scratch[SCRATCH_ELEMS];

typedef __nv_bfloat16 bf16;
typedef __nv_bfloat162 bf162;

// ---------------------------------------------------------------------------
// Helpers
// ---------------------------------------------------------------------------
__device__ __forceinline__ float gelu_tanh(float x) {
    const float k0 = 0.7978845608028654f;
    const float k1 = 0.044715f;
    float x3 = x * x * x;
    float t  = tanhf(k0 * (x + k1 * x3));
    return 0.5f * x * (1.0f + t);
}
__device__ __forceinline__ float head_scale(float rv) {
    const float c = (float)(0.25 * 3.14159265358979323846 * (1.0 - 1e-7));
    float s = sinf(rv);
    return tanf(c * (1.0f + s));
}
__device__ __forceinline__ uint32_t smem_u32(const void* p) {
    uint32_t a;
    asm("{ .reg .u64 t; cvta.to.shared.u64 t, %1; cvt.u32.u64 %0, t; }" : "=r"(a) : "l"(p));
    return a;
}
__device__ __forceinline__ void split_store(float v0, float v1, bf16* H, bf16* L, size_t idx) {
    bf162 hi2 = __floats2bfloat162_rn(v0, v1);
    float2 hf = __bfloat1622float2(hi2);
    bf162 lo2 = __floats2bfloat162_rn(v0 - hf.x, v1 - hf.y);
    *(bf162*)(H + idx) = hi2;
    *(bf162*)(L + idx) = lo2;
}
__device__ __forceinline__ void split_store1(float v, bf16* H, bf16* L, size_t idx) {
    bf16 h = __float2bfloat16(v);
    H[idx] = h;
    L[idx] = __float2bfloat16(v - __bfloat162float(h));
}

__device__ __forceinline__ void mma_bf16(float* d, const uint32_t* a, const uint32_t* b) {
    asm volatile(
        "mma.sync.aligned.m16n8k16.row.col.f32.bf16.bf16.f32 "
        "{%0,%1,%2,%3}, {%4,%5,%6,%7}, {%8,%9}, {%0,%1,%2,%3};"
        : "+f"(d[0]), "+f"(d[1]), "+f"(d[2]), "+f"(d[3])
        : "r"(a[0]), "r"(a[1]), "r"(a[2]), "r"(a[3]), "r"(b[0]), "r"(b[1]));
}
#define LDSM_X4(r0, r1, r2, r3, addr) \
    asm volatile("ldmatrix.sync.aligned.m8n8.x4.shared.b16 {%0,%1,%2,%3}, [%4];" \
                 : "=r"(r0), "=r"(r1), "=r"(r2), "=r"(r3) : "r"(addr))
__device__ __forceinline__ void cpa16(uint32_t dst, const void* src) {
    asm volatile("cp.async.cg.shared.global [%0], [%1], 16;" :: "r"(dst), "l"(src));
}

// ---------------------------------------------------------------------------
// Encoder: h = gelu(x @ W4x256 + b) -> hi/lo planes (pairs)
// ---------------------------------------------------------------------------
__global__ void k_encoder(const float* __restrict__ x,
                          const float* __restrict__ w,
                          const float* __restrict__ bias,
                          bf16* __restrict__ outH, bf16* __restrict__ outL) {
    int pid = blockIdx.x * blockDim.x + threadIdx.x;   // B*NF*CC/2
    int m = pid >> 7;
    int c = (pid & 127) * 2;
    const float* xr = x + (size_t)m * 4;
    float x0 = xr[0], x1 = xr[1], x2 = xr[2], x3 = xr[3];
    float v0 = bias[c]   + x0 * w[c]   + x1 * w[256 + c]   + x2 * w[512 + c]   + x3 * w[768 + c];
    float v1 = bias[c+1] + x0 * w[c+1] + x1 * w[256 + c+1] + x2 * w[512 + c+1] + x3 * w[768 + c+1];
    split_store(gelu_tanh(v0), gelu_tanh(v1), outH, outL, (size_t)pid * 2);
}

// ---------------------------------------------------------------------------
// Weight prep: -> wt[n][k] hi/lo planes
// ---------------------------------------------------------------------------
__global__ void k_prep_whead(const float* __restrict__ w_hcv,
                             bf16* __restrict__ wtH, bf16* __restrict__ wtL) {
    int idx = blockIdx.x * blockDim.x + threadIdx.x;   // 65536
    int n = idx >> 8;       // h*32+v
    int k = idx & 255;
    int h = n >> 5, v = n & 31;
    split_store1(w_hcv[(size_t)h * CC * VD + (size_t)k * VD + v], wtH, wtL, idx);
}
__global__ void k_prep_wT(const float* __restrict__ w,
                          bf16* __restrict__ wtH, bf16* __restrict__ wtL) {
    int idx = blockIdx.x * blockDim.x + threadIdx.x;   // 65536
    int n = idx >> 8;
    int k = idx & 255;
    split_store1(w[(size_t)k * 256 + n], wtH, wtL, idx);
}

// ---------------------------------------------------------------------------
// Per-head per-plane transpose: [h][s][256] -> [h][256][s]  (bf16)
// ---------------------------------------------------------------------------
__global__ void k_transp(const bf16* __restrict__ in, bf16* __restrict__ out, int s) {
    __shared__ bf16 t[32][33];
    int hh = blockIdx.z;
    in  += (size_t)hh * s * 256;
    out += (size_t)hh * s * 256;
    int kb = blockIdx.x * 32;
    int nb = blockIdx.y * 32;
    int x = threadIdx.x, y = threadIdx.y;   // (32, 8)
#pragma unroll
    for (int i = 0; i < 32; i += 8)
        t[y + i][x] = in[(size_t)(kb + y + i) * 256 + nb + x];
    __syncthreads();
#pragma unroll
    for (int i = 0; i < 32; i += 8)
        out[(size_t)(nb + y + i) * s + kb + x] = t[x][y + i];
}

// ---------------------------------------------------------------------------
// Global attention: softmax(-md*scale) -> hi/lo planes
// ---------------------------------------------------------------------------
__global__ void k_att_global(const float* __restrict__ md,
                             const float* __restrict__ r,
                             bf16* __restrict__ dH, bf16* __restrict__ dL,
                             int Nq, int Nk) {
    extern __shared__ float sm[];
    float* row = sm;
    float* red = sm + Nk;
    int rowid = blockIdx.x;
    int h = rowid / Nq;
    float scale = head_scale(r[h]);
    const float* src = md + (size_t)rowid * Nk;
    bf16* dstH = dH + (size_t)rowid * Nk;
    bf16* dstL = dL + (size_t)rowid * Nk;
    int tid = threadIdx.x;

    float mn = 3.402823466e+38f;
    for (int k = tid; k < Nk; k += 256) {
        float v = src[k] * scale;
        row[k] = v;
        mn = fminf(mn, v);
    }
    red[tid] = mn; __syncthreads();
    for (int s = 128; s > 0; s >>= 1) {
        if (tid < s) red[tid] = fminf(red[tid], red[tid + s]);
        __syncthreads();
    }
    mn = red[0];
    __syncthreads();

    float sum = 0.0f;
    for (int k = tid; k < Nk; k += 256) {
        float e = expf(mn - row[k]);
        row[k] = e;
        sum += e;
    }
    red[tid] = sum; __syncthreads();
    for (int s = 128; s > 0; s >>= 1) {
        if (tid < s) red[tid] += red[tid + s];
        __syncthreads();
    }
    float inv = 1.0f / red[0];
    for (int k = tid * 2; k < Nk; k += 512)
        split_store(row[k] * inv, row[k + 1] * inv, dstH, dstL, (size_t)k);
}

// ---------------------------------------------------------------------------
// Masked attention (locality 30, Nk=1024) -> hi/lo planes
// ---------------------------------------------------------------------------
__global__ void k_att_masked(const float* __restrict__ md,
                             const float* __restrict__ r,
                             bf16* __restrict__ dH, bf16* __restrict__ dL) {
    __shared__ float vals[NL];
    __shared__ float srt[NL];
    __shared__ float red[256];
    int rowid = blockIdx.x;           // h*NL + q
    int h = rowid / NL;
    float scale = head_scale(r[h]);
    const float* src = md + (size_t)rowid * NL;
    bf16* dstH = dH + (size_t)rowid * NL;
    bf16* dstL = dL + (size_t)rowid * NL;
    int tid = threadIdx.x;

    for (int k = tid; k < NL; k += 256) {
        float v = src[k] * scale;
        vals[k] = v;
        srt[k]  = v;
    }
    __syncthreads();

    // Bitonic sort ascending (1024)
    for (int k = 2; k <= NL; k <<= 1) {
        for (int j = k >> 1; j > 0; j >>= 1) {
            for (int i = tid; i < NL; i += 256) {
                int ixj = i ^ j;
                if (ixj > i) {
                    bool up = ((i & k) == 0);
                    float a = srt[i], b = srt[ixj];
                    if ((a > b) == up) { srt[i] = b; srt[ixj] = a; }
                }
            }
            __syncthreads();
        }
    }

    // percentile(30): idx 0.3*1023 = 306.9
    float a306 = srt[306], a307 = srt[307];
    float thr = a306 + 0.9f * (a307 - a306);
    float mn  = srt[0];

    float sum = 0.0f;
    for (int k = tid; k < NL; k += 256) {
        float v = vals[k];
        float e = (v <= thr) ? expf(mn - v) : 0.0f;
        vals[k] = e;
        sum += e;
    }
    red[tid] = sum; __syncthreads();
    for (int s = 128; s > 0; s >>= 1) {
        if (tid < s) red[tid] += red[tid + s];
        __syncthreads();
    }
    float inv = 1.0f / red[0];
    for (int k = tid * 2; k < NL; k += 512)
        split_store(vals[k] * inv, vals[k + 1] * inv, dstH, dstL, (size_t)k);
}

// ---------------------------------------------------------------------------
// Split-bf16 MMA GEMM with cp.async + ldmatrix.
// C[128x64 tile] = epilogue(A[M,K] @ B[256,K]^T)  (B stored [n][k])
// Operands: separate bf16 hi/lo planes. 3-term: AhBh + AhBl + AlBh (fp32 acc).
// 128 threads, 4 warps (2M x 2N), warp tile 64x32, k-chunk 32, double buffer.
// grid: (M/128, 4, nHeads). K % 32 == 0.
// flags: bit0 gelu, bit1 add addbuf. store_mode: 0 plain, 1 att, 2 val.
// Smem per stage: A 2*10240 + B 2*5120 = 30720 B; 2 stages = 61440 B.
// ---------------------------------------------------------------------------
#define STG_BYTES 30720
#define GB_SMEM   (2 * STG_BYTES)

__global__ void __launch_bounds__(128)
k_gbf(const bf16* __restrict__ AH, const bf16* __restrict__ AL,
      const bf16* __restrict__ BH, const bf16* __restrict__ BL,
      bf16* __restrict__ CH, bf16* __restrict__ CL,
      int K, size_t aStr, size_t bStr,
      const float* __restrict__ bias,
      const bf16* __restrict__ addH, const bf16* __restrict__ addL,
      int flags, int store_mode, int s_param)
{
    extern __shared__ char dsm[];
    const int h = blockIdx.z;
    const size_t aoff = (size_t)h * aStr + (size_t)blockIdx.x * 128 * K;
    const size_t boff = (size_t)h * bStr + (size_t)blockIdx.y * 64 * K;
    AH += aoff; AL += aoff;
    BH += boff; BL += boff;

    const uint32_t sb = smem_u32(dsm);
    const int tid  = threadIdx.x;
    const int lane = tid & 31;
    const int warp = tid >> 5;
    const int wm   = warp & 1;
    const int wn   = warp >> 1;

    float acc[4][4][4];
#pragma unroll
    for (int mi = 0; mi < 4; mi++)
#pragma unroll
        for (int ni = 0; ni < 4; ni++)
#pragma unroll
            for (int q = 0; q < 4; q++) acc[mi][ni][q] = 0.0f;

    const int KT = K >> 5;

    auto ISSUE = [&](int kt) {
        int k0 = kt * 32;
        uint32_t base = sb + (kt & 1) * STG_BYTES;
        // A: 128 rows x 4 segs x 2 planes = 1024 chunks, 8 per thread
#pragma unroll
        for (int p = 0; p < 8; p++) {
            int id = tid + p * 128;
            int pl = id >> 9, rem = id & 511;
            int row = rem >> 2, seg = rem & 3;
            const bf16* src = (pl ? AL : AH) + (size_t)row * K + k0 + seg * 8;
            cpa16(base + pl * 10240 + row * 80 + seg * 16, src);
        }
        // B: 64 rows x 4 segs x 2 planes = 512 chunks, 4 per thread
#pragma unroll
        for (int p = 0; p < 4; p++) {
            int id = tid + p * 128;
            int pl = id >> 8, rem = id & 255;
            int row = rem >> 2, seg = rem & 3;
            const bf16* src = (pl ? BL : BH) + (size_t)row * K + k0 + seg * 8;
            cpa16(base + 20480 + pl * 5120 + row * 80 + seg * 16, src);
        }
        asm volatile("cp.async.commit_group;");
    };

    auto COMPUTE = [&](int stage) {
        uint32_t base = sb + stage * STG_BYTES;
#pragma unroll
        for (int kk = 0; kk < 2; kk++) {
            uint32_t aH4[4][4], aL4[4][4], bH2[4][2], bL2[4][2];
#pragma unroll
            for (int mi = 0; mi < 4; mi++) {
                uint32_t ao = (uint32_t)(wm * 64 + mi * 16 + (lane & 15)) * 80
                            + kk * 32 + ((lane >> 4) & 1) * 16;
                LDSM_X4(aH4[mi][0], aH4[mi][1], aH4[mi][2], aH4[mi][3], base + ao);
                LDSM_X4(aL4[mi][0], aL4[mi][1], aL4[mi][2], aL4[mi][3], base + 10240 + ao);
            }
#pragma unroll
            for (int nj = 0; nj < 2; nj++) {
                uint32_t bo = (uint32_t)(wn * 32 + nj * 16 + (lane & 7) + ((lane >> 4) & 1) * 8) * 80
                            + kk * 32 + ((lane >> 3) & 1) * 16;
                uint32_t t0, t1, t2, t3;
                LDSM_X4(t0, t1, t2, t3, base + 20480 + bo);
                bH2[nj*2][0] = t0; bH2[nj*2][1] = t1; bH2[nj*2+1][0] = t2; bH2[nj*2+1][1] = t3;
                LDSM_X4(t0, t1, t2, t3, base + 20480 + 5120 + bo);
                bL2[nj*2][0] = t0; bL2[nj*2][1] = t1; bL2[nj*2+1][0] = t2; bL2[nj*2+1][1] = t3;
            }
#pragma unroll
            for (int mi = 0; mi < 4; mi++)
#pragma unroll
                for (int ni = 0; ni < 4; ni++) {
                    mma_bf16(acc[mi][ni], aH4[mi], bH2[ni]);
                    mma_bf16(acc[mi][ni], aH4[mi], bL2[ni]);
                    mma_bf16(acc[mi][ni], aL4[mi], bH2[ni]);
                }
        }
    };

    ISSUE(0);
    for (int kt = 0; kt < KT; kt++) {
        if (kt + 1 < KT) {
            ISSUE(kt + 1);
            asm volatile("cp.async.wait_group 1;");
        } else {
            asm volatile("cp.async.wait_group 0;");
        }
        __syncthreads();
        COMPUTE(kt & 1);
        __syncthreads();
    }

    // ---- epilogue ----
    const int gr = lane >> 2;
    const int gc = lane & 3;
#pragma unroll
    for (int mi = 0; mi < 4; mi++) {
#pragma unroll
        for (int hf = 0; hf < 2; hf++) {
            int m = blockIdx.x * 128 + wm * 64 + mi * 16 + gr + hf * 8;
#pragma unroll
            for (int ni = 0; ni < 4; ni++) {
                int n = blockIdx.y * 64 + wn * 32 + ni * 8 + gc * 2;
                float v0 = acc[mi][ni][hf * 2 + 0];
                float v1 = acc[mi][ni][hf * 2 + 1];
                if (bias) { v0 += bias[n]; v1 += bias[n + 1]; }
                size_t midx = (size_t)m * 256 + n;
                if (flags & 2) {
                    bf162 ah = *(const bf162*)(addH + midx);
                    bf162 al = *(const bf162*)(addL + midx);
                    float2 ahf = __bfloat1622float2(ah);
                    float2 alf = __bfloat1622float2(al);
                    v0 += ahf.x + alf.x;
                    v1 += ahf.y + alf.y;
                }
                if (flags & 1) { v0 = gelu_tanh(v0); v1 = gelu_tanh(v1); }
                size_t idx;
                if (store_mode == 0) {
                    idx = midx;
                } else if (store_mode == 1) {
                    int bb = n >> 5, vv = n & 31;
                    idx = (size_t)bb * s_param * 256 + (size_t)m * 256 + (size_t)h * 32 + vv;
                } else {
                    int bb = m / s_param, kp = m % s_param;
                    int hh = n >> 5, vv = n & 31;
                    idx = (size_t)hh * s_param * 256 + (size_t)kp * 256 + (size_t)bb * 32 + vv;
                }
                split_store(v0, v1, CH, CL, idx);
            }
        }
    }
}

// ---------------------------------------------------------------------------
// Final projection: out[m] = sum_k (AH+AL)[m,k] * w[k] + b   (one warp/row)
// ---------------------------------------------------------------------------
__global__ void k_fc2(const bf16* __restrict__ AH, const bf16* __restrict__ AL,
                      const float* __restrict__ w,
                      const float* __restrict__ b, float* __restrict__ out, int M) {
    int gwarp = (blockIdx.x * blockDim.x + threadIdx.x) >> 5;
    int lane = threadIdx.x & 31;
    if (gwarp >= M) return;
    const bf16* aH = AH + (size_t)gwarp * 256;
    const bf16* aL = AL + (size_t)gwarp * 256;
    float s = 0.0f;
#pragma unroll
    for (int k = lane; k < 256; k += 32)
        s += (__bfloat162float(aH[k]) + __bfloat162float(aL[k])) * w[k];
#pragma unroll
    for (int off = 16; off > 0; off >>= 1)
        s += __shfl_down_sync(0xFFFFFFFFu, s, off);
    if (lane == 0) out[gwarp] = s + b[0];
}

// ---------------------------------------------------------------------------
// Host orchestration
// ---------------------------------------------------------------------------
extern "C" void kernel_launch(void* const* d_in, const int* in_sizes, int n_in,
                              void* d_out, int out_size) {
    (void)in_sizes; (void)n_in; (void)out_size;

    const float* x       = (const float*)d_in[0];
    const float* md_down = (const float*)d_in[1];
    const float* md_p[2] = {(const float*)d_in[2], (const float*)d_in[3]};
    const float* md_up   = (const float*)d_in[4];
    const float* en_w    = (const float*)d_in[5];
    const float* en_b    = (const float*)d_in[6];
    const float* down_r  = (const float*)d_in[7];
    const float* down_w  = (const float*)d_in[8];
    const float* pa_r[2] = {(const float*)d_in[9],  (const float*)d_in[17]};
    const float* pa_w[2] = {(const float*)d_in[10], (const float*)d_in[18]};
    const float* f1w[2]  = {(const float*)d_in[11], (const float*)d_in[19]};
    const float* f1b[2]  = {(const float*)d_in[12], (const float*)d_in[20]};
    const float* f2w[2]  = {(const float*)d_in[13], (const float*)d_in[21]};
    const float* f2b[2]  = {(const float*)d_in[14], (const float*)d_in[22]};
    const float* rw[2]   = {(const float*)d_in[15], (const float*)d_in[23]};
    const float* rb[2]   = {(const float*)d_in[16], (const float*)d_in[24]};
    const float* up_r    = (const float*)d_in[25];
    const float* up_w    = (const float*)d_in[26];
    const float* de1w    = (const float*)d_in[27];
    const float* de1b    = (const float*)d_in[28];
    const float* de2w    = (const float*)d_in[29];
    const float* de2b    = (const float*)d_in[30];

    cudaFuncSetAttribute(k_gbf, cudaFuncAttributeMaxDynamicSharedMemorySize, GB_SMEM);

    float* S = nullptr;
    cudaGetSymbolAddress((void**)&S, g_scratch);
    bf16* attH  = (bf16*)(S + OFF_ATT_H);
    bf16* attL  = (bf16*)(S + OFF_ATT_L);
    bf16* attpH = (bf16*)(S + OFF_ATTP_H);
    bf16* attpL = (bf16*)(S + OFF_ATTP_L);
    bf16* valH  = (bf16*)(S + OFF_VAL_H);
    bf16* valL  = (bf16*)(S + OFF_VAL_L);
    bf16* valtH = (bf16*)(S + OFF_VALT_H);
    bf16* valtL = (bf16*)(S + OFF_VALT_L);
    bf16* hfH   = (bf16*)(S + OFF_HF_H);
    bf16* hfL   = (bf16*)(S + OFF_HF_L);
    bf16* tmpH  = (bf16*)(S + OFF_TMP_H);
    bf16* tmpL  = (bf16*)(S + OFF_TMP_L);
    bf16* latH[3], *latL[3];
    for (int i = 0; i < 3; i++) {
        latH[i] = (bf16*)(S + OFF_LAT + (2 * i    ) * W_LAT);
        latL[i] = (bf16*)(S + OFF_LAT + (2 * i + 1) * W_LAT);
    }
    bf16* wtH = (bf16*)(S + OFF_WT_H);
    bf16* wtL = (bf16*)(S + OFF_WT_L);

    // ---- encoder ----
    k_encoder<<<(BB * NF * CC / 2) / 256, 256>>>(x, en_w, en_b, hfH, hfL);

    // ---- down attention (global, Nq=1024, Nk=4096) ----
    k_prep_whead<<<256, 256>>>(down_w, wtH, wtL);
    k_gbf<<<dim3(BB * NF / 128, 4, 1), 128, GB_SMEM>>>(
        hfH, hfL, wtH, wtL, valH, valL, 256, 0, 0,
        nullptr, nullptr, nullptr, 0, 2, NF);
    k_transp<<<dim3(NF / 32, 8, HH), dim3(32, 8)>>>(valH, valtH, NF);
    k_transp<<<dim3(NF / 32, 8, HH), dim3(32, 8)>>>(valL, valtL, NF);
    k_att_global<<<HH * NL, 256, (NF + 256) * sizeof(float)>>>(md_down, down_r, attH, attL, NL, NF);
    k_gbf<<<dim3(NL / 128, 4, HH), 128, GB_SMEM>>>(
        attH, attL, valtH, valtL, latH[0], latL[0], NF,
        (size_t)NL * NF, (size_t)256 * NF,
        nullptr, nullptr, nullptr, 1, 1, NL);

    // ---- two latent PiT blocks (masked attention, locality=30) ----
    int ih = 0, ip = 1, it = 2;
    for (int i = 0; i < 2; i++) {
        k_prep_whead<<<256, 256>>>(pa_w[i], wtH, wtL);
        k_gbf<<<dim3(BB * NL / 128, 4, 1), 128, GB_SMEM>>>(
            latH[ih], latL[ih], wtH, wtL, valH, valL, 256, 0, 0,
            nullptr, nullptr, nullptr, 0, 2, NL);
        k_transp<<<dim3(NL / 32, 8, HH), dim3(32, 8)>>>(valH, valtH, NL);
        k_transp<<<dim3(NL / 32, 8, HH), dim3(32, 8)>>>(valL, valtL, NL);
        k_att_masked<<<HH * NL, 256>>>(md_p[i], pa_r[i], attpH, attpL);
        k_gbf<<<dim3(NL / 128, 4, HH), 128, GB_SMEM>>>(
            attpH, attpL, valtH, valtL, latH[ip], latL[ip], NL,
            (size_t)NL * NL, (size_t)256 * NL,
            nullptr, nullptr, nullptr, 1, 1, NL);
        // mlp fc1 (gelu)
        k_prep_wT<<<256, 256>>>(f1w[i], wtH, wtL);
        k_gbf<<<dim3(BB * NL / 128, 4, 1), 128, GB_SMEM>>>(
            latH[ip], latL[ip], wtH, wtL, latH[it], latL[it], 256, 0, 0,
            f1b[i], nullptr, nullptr, 1, 0, 0);
        // mlp fc2 -> overwrite ip
        k_prep_wT<<<256, 256>>>(f2w[i], wtH, wtL);
        k_gbf<<<dim3(BB * NL / 128, 4, 1), 128, GB_SMEM>>>(
            latH[it], latL[it], wtH, wtL, latH[ip], latL[ip], 256, 0, 0,
            f2b[i], nullptr, nullptr, 0, 0, 0);
        // h = gelu(mlp + hin@rw + rb) -> it
        k_prep_wT<<<256, 256>>>(rw[i], wtH, wtL);
        k_gbf<<<dim3(BB * NL / 128, 4, 1), 128, GB_SMEM>>>(
            latH[ih], latL[ih], wtH, wtL, latH[it], latL[it], 256, 0, 0,
            rb[i], latH[ip], latL[ip], 3, 0, 0);
        int t = ih; ih = it; it = t;
    }

    // ---- up attention (global, Nq=4096, Nk=1024) ----
    k_prep_whead<<<256, 256>>>(up_w, wtH, wtL);
    k_gbf<<<dim3(BB * NL / 128, 4, 1), 128, GB_SMEM>>>(
        latH[ih], latL[ih], wtH, wtL, valH, valL, 256, 0, 0,
        nullptr, nullptr, nullptr, 0, 2, NL);
    k_transp<<<dim3(NL / 32, 8, HH), dim3(32, 8)>>>(valH, valtH, NL);
    k_transp<<<dim3(NL / 32, 8, HH), dim3(32, 8)>>>(valL, valtL, NL);
    k_att_global<<<HH * NF, 256, (NL + 256) * sizeof(float)>>>(md_up, up_r, attH, attL, NF, NL);
    k_gbf<<<dim3(NF / 128, 4, HH), 128, GB_SMEM>>>(
        attH, attL, valtH, valtL, hfH, hfL, NL,
        (size_t)NF * NL, (size_t)256 * NL,
        nullptr, nullptr, nullptr, 1, 1, NF);

    // ---- decoder ----
    k_prep_wT<<<256, 256>>>(de1w, wtH, wtL);
    k_gbf<<<dim3(BB * NF / 128, 4, 1), 128, GB_SMEM>>>(
        hfH, hfL, wtH, wtL, tmpH, tmpL, 256, 0, 0,
        de1b, nullptr, nullptr, 1, 0, 0);
    k_fc2<<<(BB * NF * 32) / 256, 256>>>(tmpH, tmpL, de2w, de2b, (float*)d_out, BB * NF);
}

// round 16
// speedup vs baseline: 1.2321x; 1.1466x over previous
#include <cuda_runtime.h>
#include <cuda_fp16.h>
#include <cstdint>
#include <cstddef>
#include <math.h>

// ---------------------------------------------------------------------------
// Problem constants
// ---------------------------------------------------------------------------
#define BB   8       // batch
#define NF   4096    // N_FULL
#define NL   1024    // N_LAT
#define CC   256     // channels
#define HH   8       // heads
#define VD   32      // C / H

// ---------------------------------------------------------------------------
// Scratch layout (words of 4 bytes inside g_scratch)
//  - activations & attention: single fp16 plane
//  - weights & value tensors: fp16 hi + lo planes
//  - residual/mlp + decoder-fc1 outputs: fp32
// ---------------------------------------------------------------------------
static const size_t W_ATT   = (size_t)HH * NL * NF / 2;  // halves/2
static const size_t W_ATTP  = (size_t)HH * NL * NL / 2;
static const size_t W_PLN   = (size_t)BB * NF * CC / 2;  // big half plane
static const size_t W_LATP  = (size_t)BB * NL * CC / 2;  // lat half plane
static const size_t W_MLP32 = (size_t)BB * NL * CC;      // fp32
static const size_t W_TMP32 = (size_t)BB * NF * CC;      // fp32
static const size_t W_WT    = (size_t)CC * CC / 2;

static const size_t OFF_ATT    = 0;
static const size_t OFF_ATTP   = OFF_ATT    + W_ATT;
static const size_t OFF_VAL_H  = OFF_ATTP   + W_ATTP;
static const size_t OFF_VAL_L  = OFF_VAL_H  + W_PLN;
static const size_t OFF_VALT_H = OFF_VAL_L  + W_PLN;
static const size_t OFF_VALT_L = OFF_VALT_H + W_PLN;
static const size_t OFF_HF     = OFF_VALT_L + W_PLN;
static const size_t OFF_LAT    = OFF_HF     + W_PLN;     // 3 single planes
static const size_t OFF_MLP32  = OFF_LAT    + 3 * W_LATP;
static const size_t OFF_TMP32  = OFF_MLP32  + W_MLP32;
static const size_t OFF_WT_H   = OFF_TMP32  + W_TMP32;
static const size_t OFF_WT_L   = OFF_WT_H   + W_WT;
static const size_t SCRATCH_ELEMS = OFF_WT_L + W_WT;

__device__ float g_scratch[SCRATCH_ELEMS];

// ---------------------------------------------------------------------------
// Helpers
// ---------------------------------------------------------------------------
__device__ __forceinline__ float gelu_tanh(float x) {
    const float k0 = 0.7978845608028654f;
    const float k1 = 0.044715f;
    float x3 = x * x * x;
    float t  = tanhf(k0 * (x + k1 * x3));
    return 0.5f * x * (1.0f + t);
}
__device__ __forceinline__ float head_scale(float rv) {
    const float c = (float)(0.25 * 3.14159265358979323846 * (1.0 - 1e-7));
    float s = sinf(rv);
    return tanf(c * (1.0f + s));
}
__device__ __forceinline__ uint32_t smem_u32(const void* p) {
    uint32_t a;
    asm("{ .reg .u64 t; cvta.to.shared.u64 t, %1; cvt.u32.u64 %0, t; }" : "=r"(a) : "l"(p));
    return a;
}
// split x (pre-scaled) into fp16 hi + fp16 lo
__device__ __forceinline__ void hsplit(float x, __half& h, __half& l) {
    h = __float2half_rn(x);
    l = __float2half_rn(x - __half2float(h));
}
__device__ __forceinline__ void mma_f16(float* d, const uint32_t* a, const uint32_t* b) {
    asm volatile(
        "mma.sync.aligned.m16n8k16.row.col.f32.f16.f16.f32 "
        "{%0,%1,%2,%3}, {%4,%5,%6,%7}, {%8,%9}, {%0,%1,%2,%3};"
        : "+f"(d[0]), "+f"(d[1]), "+f"(d[2]), "+f"(d[3])
        : "r"(a[0]), "r"(a[1]), "r"(a[2]), "r"(a[3]), "r"(b[0]), "r"(b[1]));
}
#define LDSM_X4(r0, r1, r2, r3, addr) \
    asm volatile("ldmatrix.sync.aligned.m8n8.x4.shared.b16 {%0,%1,%2,%3}, [%4];" \
                 : "=r"(r0), "=r"(r1), "=r"(r2), "=r"(r3) : "r"(addr))
__device__ __forceinline__ void cpa16(uint32_t dst, const void* src) {
    asm volatile("cp.async.cg.shared.global [%0], [%1], 16;" :: "r"(dst), "l"(src));
}

// ---------------------------------------------------------------------------
// Encoder: h = gelu(x @ W4x256 + b) -> single fp16 plane
// ---------------------------------------------------------------------------
__global__ void k_encoder(const float* __restrict__ x,
                          const float* __restrict__ w,
                          const float* __restrict__ bias,
                          __half* __restrict__ out) {
    int pid = blockIdx.x * blockDim.x + threadIdx.x;   // B*NF*CC/2
    int m = pid >> 7;
    int c = (pid & 127) * 2;
    const float* xr = x + (size_t)m * 4;
    float x0 = xr[0], x1 = xr[1], x2 = xr[2], x3 = xr[3];
    float v0 = bias[c]   + x0 * w[c]   + x1 * w[256 + c]   + x2 * w[512 + c]   + x3 * w[768 + c];
    float v1 = bias[c+1] + x0 * w[c+1] + x1 * w[256 + c+1] + x2 * w[512 + c+1] + x3 * w[768 + c+1];
    *(__half2*)(out + (size_t)pid * 2) =
        __floats2half2_rn(gelu_tanh(v0), gelu_tanh(v1));
}

// ---------------------------------------------------------------------------
// Weight prep: wt[n][k] = 16*w, hi/lo fp16 planes (x16 keeps lo normal)
// ---------------------------------------------------------------------------
__global__ void k_prep_whead(const float* __restrict__ w_hcv,
                             __half* __restrict__ wtH, __half* __restrict__ wtL) {
    int idx = blockIdx.x * blockDim.x + threadIdx.x;   // 65536
    int n = idx >> 8;       // h*32+v
    int k = idx & 255;
    int h = n >> 5, v = n & 31;
    __half hi, lo;
    hsplit(16.0f * w_hcv[(size_t)h * CC * VD + (size_t)k * VD + v], hi, lo);
    wtH[idx] = hi; wtL[idx] = lo;
}
__global__ void k_prep_wT(const float* __restrict__ w,
                          __half* __restrict__ wtH, __half* __restrict__ wtL) {
    int idx = blockIdx.x * blockDim.x + threadIdx.x;   // 65536
    int n = idx >> 8;
    int k = idx & 255;
    __half hi, lo;
    hsplit(16.0f * w[(size_t)k * 256 + n], hi, lo);
    wtH[idx] = hi; wtL[idx] = lo;
}

// ---------------------------------------------------------------------------
// Per-head transpose of two fp16 planes: [h][s][256] -> [h][256][s]
// ---------------------------------------------------------------------------
__global__ void k_transp2(const __half* __restrict__ inH, const __half* __restrict__ inL,
                          __half* __restrict__ outH, __half* __restrict__ outL, int s) {
    __shared__ __half tH[32][33];
    __shared__ __half tL[32][33];
    int hh = blockIdx.z;
    size_t base = (size_t)hh * s * 256;
    int kb = blockIdx.x * 32;
    int nb = blockIdx.y * 32;
    int x = threadIdx.x, y = threadIdx.y;   // (32, 8)
#pragma unroll
    for (int i = 0; i < 32; i += 8) {
        size_t src = base + (size_t)(kb + y + i) * 256 + nb + x;
        tH[y + i][x] = inH[src];
        tL[y + i][x] = inL[src];
    }
    __syncthreads();
#pragma unroll
    for (int i = 0; i < 32; i += 8) {
        size_t dst = base + (size_t)(nb + y + i) * s + kb + x;
        outH[dst] = tH[x][y + i];
        outL[dst] = tL[x][y + i];
    }
}

// ---------------------------------------------------------------------------
// Global attention: softmax(-md*scale) -> single fp16 plane
// ---------------------------------------------------------------------------
__global__ void k_att_global(const float* __restrict__ md,
                             const float* __restrict__ r,
                             __half* __restrict__ dA,
                             int Nq, int Nk) {
    extern __shared__ float sm[];
    float* row = sm;
    float* red = sm + Nk;
    int rowid = blockIdx.x;
    int h = rowid / Nq;
    float scale = head_scale(r[h]);
    const float* src = md + (size_t)rowid * Nk;
    __half* dst = dA + (size_t)rowid * Nk;
    int tid = threadIdx.x;

    float mn = 3.402823466e+38f;
    for (int k = tid; k < Nk; k += 256) {
        float v = src[k] * scale;
        row[k] = v;
        mn = fminf(mn, v);
    }
    red[tid] = mn; __syncthreads();
    for (int s = 128; s > 0; s >>= 1) {
        if (tid < s) red[tid] = fminf(red[tid], red[tid + s]);
        __syncthreads();
    }
    mn = red[0];
    __syncthreads();

    float sum = 0.0f;
    for (int k = tid; k < Nk; k += 256) {
        float e = expf(mn - row[k]);
        row[k] = e;
        sum += e;
    }
    red[tid] = sum; __syncthreads();
    for (int s = 128; s > 0; s >>= 1) {
        if (tid < s) red[tid] += red[tid + s];
        __syncthreads();
    }
    float inv = 1.0f / red[0];
    for (int k = tid * 2; k < Nk; k += 512)
        *(__half2*)(dst + k) = __floats2half2_rn(row[k] * inv, row[k + 1] * inv);
}

// ---------------------------------------------------------------------------
// Masked attention (locality 30, Nk=1024) -> single fp16 plane
// ---------------------------------------------------------------------------
__global__ void k_att_masked(const float* __restrict__ md,
                             const float* __restrict__ r,
                             __half* __restrict__ dA) {
    __shared__ float vals[NL];
    __shared__ float srt[NL];
    __shared__ float red[256];
    int rowid = blockIdx.x;           // h*NL + q
    int h = rowid / NL;
    float scale = head_scale(r[h]);
    const float* src = md + (size_t)rowid * NL;
    __half* dst = dA + (size_t)rowid * NL;
    int tid = threadIdx.x;

    for (int k = tid; k < NL; k += 256) {
        float v = src[k] * scale;
        vals[k] = v;
        srt[k]  = v;
    }
    __syncthreads();

    // Bitonic sort ascending (1024)
    for (int k = 2; k <= NL; k <<= 1) {
        for (int j = k >> 1; j > 0; j >>= 1) {
            for (int i = tid; i < NL; i += 256) {
                int ixj = i ^ j;
                if (ixj > i) {
                    bool up = ((i & k) == 0);
                    float a = srt[i], b = srt[ixj];
                    if ((a > b) == up) { srt[i] = b; srt[ixj] = a; }
                }
            }
            __syncthreads();
        }
    }

    // percentile(30): idx 0.3*1023 = 306.9
    float a306 = srt[306], a307 = srt[307];
    float thr = a306 + 0.9f * (a307 - a306);
    float mn  = srt[0];

    float sum = 0.0f;
    for (int k = tid; k < NL; k += 256) {
        float v = vals[k];
        float e = (v <= thr) ? expf(mn - v) : 0.0f;
        vals[k] = e;
        sum += e;
    }
    red[tid] = sum; __syncthreads();
    for (int s = 128; s > 0; s >>= 1) {
        if (tid < s) red[tid] += red[tid + s];
        __syncthreads();
    }
    float inv = 1.0f / red[0];
    for (int k = tid * 2; k < NL; k += 512)
        *(__half2*)(dst + k) = __floats2half2_rn(vals[k] * inv, vals[k + 1] * inv);
}

// ---------------------------------------------------------------------------
// fp16 2-MMA GEMM: C = epilogue(outScale * (A @ (Bh+Bl)^T))
//  A[M,K] single fp16 plane (row-major), B stored [n][k] fp16 hi/lo planes.
//  D += A*Bh + A*Bl with fp32 accumulate -> B exact to 2^-22, error = A's u.
// 128 threads, 4 warps (2M x 2N), block 128x64, warp 64x32, k-chunk 32,
// double-buffered cp.async + ldmatrix (addressing identical to R13, verified).
// grid: (M/128, 4, nHeads).
// flags: bit0 gelu, bit1 add add32 (fp32), bit2 store fp32 (mode 0 only)
// store_mode: 0 plain; 1 att-apply scatter (half); 2 value scatter (hi/lo).
// ---------------------------------------------------------------------------
#define STG 20480   // A 10240 + BH 5120 + BL 5120  (80B-padded rows)

__global__ void __launch_bounds__(128)
k_gh(const __half* __restrict__ A,
     const __half* __restrict__ BHp, const __half* __restrict__ BLp,
     void* __restrict__ Cout, __half* __restrict__ CLp,
     int K, size_t aStr, size_t bStr,
     const float* __restrict__ bias, const float* __restrict__ add32,
     float outScale, int flags, int store_mode, int s_param)
{
    __shared__ char dsm[2 * STG];
    const int h = blockIdx.z;
    A   += (size_t)h * aStr + (size_t)blockIdx.x * 128 * K;
    BHp += (size_t)h * bStr + (size_t)blockIdx.y * 64 * K;
    BLp += (size_t)h * bStr + (size_t)blockIdx.y * 64 * K;

    const uint32_t sb = smem_u32(dsm);
    const int tid  = threadIdx.x;
    const int lane = tid & 31;
    const int warp = tid >> 5;
    const int wm   = warp & 1;
    const int wn   = warp >> 1;

    float acc[4][4][4];
#pragma unroll
    for (int mi = 0; mi < 4; mi++)
#pragma unroll
        for (int ni = 0; ni < 4; ni++)
#pragma unroll
            for (int q = 0; q < 4; q++) acc[mi][ni][q] = 0.0f;

    const int KT = K >> 5;

    auto ISSUE = [&](int kt) {
        int k0 = kt * 32;
        uint32_t base = sb + (kt & 1) * STG;
        // A: 128 rows x 4 segs (16B) = 512 chunks, 4/thread
#pragma unroll
        for (int p = 0; p < 4; p++) {
            int id = tid + p * 128;
            int row = id >> 2, seg = id & 3;
            cpa16(base + row * 80 + seg * 16, A + (size_t)row * K + k0 + seg * 8);
        }
        // B: 2 planes x 64 rows x 4 segs = 512 chunks, 4/thread
#pragma unroll
        for (int p = 0; p < 4; p++) {
            int id = tid + p * 128;
            int pl = id >> 8, rem = id & 255;
            int row = rem >> 2, seg = rem & 3;
            const __half* src = (pl ? BLp : BHp) + (size_t)row * K + k0 + seg * 8;
            cpa16(base + 10240 + pl * 5120 + row * 80 + seg * 16, src);
        }
        asm volatile("cp.async.commit_group;");
    };

    auto COMPUTE = [&](int stage) {
        uint32_t base = sb + stage * STG;
#pragma unroll
        for (int kk = 0; kk < 2; kk++) {
            uint32_t a4[4][4], bH2[4][2], bL2[4][2];
#pragma unroll
            for (int mi = 0; mi < 4; mi++) {
                uint32_t ao = (uint32_t)(wm * 64 + mi * 16 + (lane & 15)) * 80
                            + kk * 32 + ((lane >> 4) & 1) * 16;
                LDSM_X4(a4[mi][0], a4[mi][1], a4[mi][2], a4[mi][3], base + ao);
            }
#pragma unroll
            for (int nj = 0; nj < 2; nj++) {
                uint32_t bo = (uint32_t)(wn * 32 + nj * 16 + (lane & 7) + ((lane >> 4) & 1) * 8) * 80
                            + kk * 32 + ((lane >> 3) & 1) * 16;
                uint32_t t0, t1, t2, t3;
                LDSM_X4(t0, t1, t2, t3, base + 10240 + bo);
                bH2[nj*2][0] = t0; bH2[nj*2][1] = t1; bH2[nj*2+1][0] = t2; bH2[nj*2+1][1] = t3;
                LDSM_X4(t0, t1, t2, t3, base + 10240 + 5120 + bo);
                bL2[nj*2][0] = t0; bL2[nj*2][1] = t1; bL2[nj*2+1][0] = t2; bL2[nj*2+1][1] = t3;
            }
#pragma unroll
            for (int mi = 0; mi < 4; mi++)
#pragma unroll
                for (int ni = 0; ni < 4; ni++) {
                    mma_f16(acc[mi][ni], a4[mi], bH2[ni]);
                    mma_f16(acc[mi][ni], a4[mi], bL2[ni]);
                }
        }
    };

    ISSUE(0);
    for (int kt = 0; kt < KT; kt++) {
        if (kt + 1 < KT) {
            ISSUE(kt + 1);
            asm volatile("cp.async.wait_group 1;");
        } else {
            asm volatile("cp.async.wait_group 0;");
        }
        __syncthreads();
        COMPUTE(kt & 1);
        __syncthreads();
    }

    // ---- epilogue ----
    const int gr = lane >> 2;
    const int gc = lane & 3;
#pragma unroll
    for (int mi = 0; mi < 4; mi++) {
#pragma unroll
        for (int hf = 0; hf < 2; hf++) {
            int m = blockIdx.x * 128 + wm * 64 + mi * 16 + gr + hf * 8;
#pragma unroll
            for (int ni = 0; ni < 4; ni++) {
                int n = blockIdx.y * 64 + wn * 32 + ni * 8 + gc * 2;
                float v0 = acc[mi][ni][hf * 2 + 0] * outScale;
                float v1 = acc[mi][ni][hf * 2 + 1] * outScale;
                if (bias) { v0 += bias[n]; v1 += bias[n + 1]; }
                size_t midx = (size_t)m * 256 + n;
                if (flags & 2) { v0 += add32[midx]; v1 += add32[midx + 1]; }
                if (flags & 1) { v0 = gelu_tanh(v0); v1 = gelu_tanh(v1); }
                if (store_mode == 0) {
                    if (flags & 4) {
                        *(float2*)((float*)Cout + midx) = make_float2(v0, v1);
                    } else {
                        *(__half2*)((__half*)Cout + midx) = __floats2half2_rn(v0, v1);
                    }
                } else if (store_mode == 1) {
                    int bb = n >> 5, vv = n & 31;
                    size_t idx = (size_t)bb * s_param * 256 + (size_t)m * 256
                               + (size_t)h * 32 + vv;
                    *(__half2*)((__half*)Cout + idx) = __floats2half2_rn(v0, v1);
                } else {
                    int bb = m / s_param, kp = m % s_param;
                    int hh = n >> 5, vv = n & 31;
                    size_t idx = (size_t)hh * s_param * 256 + (size_t)kp * 256
                               + (size_t)bb * 32 + vv;
                    __half h0, l0, h1, l1;
                    hsplit(v0, h0, l0);
                    hsplit(v1, h1, l1);
                    ((__half*)Cout)[idx]     = h0;  ((__half*)Cout)[idx + 1] = h1;
                    CLp[idx]                 = l0;  CLp[idx + 1]             = l1;
                }
            }
        }
    }
}

// ---------------------------------------------------------------------------
// Final projection: out[m] = A32[m,:] . w + b  (fp32 input, one warp/row)
// ---------------------------------------------------------------------------
__global__ void k_fc2(const float* __restrict__ A32, const float* __restrict__ w,
                      const float* __restrict__ b, float* __restrict__ out, int M) {
    int gwarp = (blockIdx.x * blockDim.x + threadIdx.x) >> 5;
    int lane = threadIdx.x & 31;
    if (gwarp >= M) return;
    const float* a = A32 + (size_t)gwarp * 256;
    float s = 0.0f;
#pragma unroll
    for (int k = lane; k < 256; k += 32) s += a[k] * w[k];
#pragma unroll
    for (int off = 16; off > 0; off >>= 1)
        s += __shfl_down_sync(0xFFFFFFFFu, s, off);
    if (lane == 0) out[gwarp] = s + b[0];
}

// ---------------------------------------------------------------------------
// Host orchestration
// ---------------------------------------------------------------------------
extern "C" void kernel_launch(void* const* d_in, const int* in_sizes, int n_in,
                              void* d_out, int out_size) {
    (void)in_sizes; (void)n_in; (void)out_size;

    const float* x       = (const float*)d_in[0];
    const float* md_down = (const float*)d_in[1];
    const float* md_p[2] = {(const float*)d_in[2], (const float*)d_in[3]};
    const float* md_up   = (const float*)d_in[4];
    const float* en_w    = (const float*)d_in[5];
    const float* en_b    = (const float*)d_in[6];
    const float* down_r  = (const float*)d_in[7];
    const float* down_w  = (const float*)d_in[8];
    const float* pa_r[2] = {(const float*)d_in[9],  (const float*)d_in[17]};
    const float* pa_w[2] = {(const float*)d_in[10], (const float*)d_in[18]};
    const float* f1w[2]  = {(const float*)d_in[11], (const float*)d_in[19]};
    const float* f1b[2]  = {(const float*)d_in[12], (const float*)d_in[20]};
    const float* f2w[2]  = {(const float*)d_in[13], (const float*)d_in[21]};
    const float* f2b[2]  = {(const float*)d_in[14], (const float*)d_in[22]};
    const float* rw[2]   = {(const float*)d_in[15], (const float*)d_in[23]};
    const float* rb[2]   = {(const float*)d_in[16], (const float*)d_in[24]};
    const float* up_r    = (const float*)d_in[25];
    const float* up_w    = (const float*)d_in[26];
    const float* de1w    = (const float*)d_in[27];
    const float* de1b    = (const float*)d_in[28];
    const float* de2w    = (const float*)d_in[29];
    const float* de2b    = (const float*)d_in[30];

    float* S = nullptr;
    cudaGetSymbolAddress((void**)&S, g_scratch);
    __half* att   = (__half*)(S + OFF_ATT);
    __half* attp  = (__half*)(S + OFF_ATTP);
    __half* valH  = (__half*)(S + OFF_VAL_H);
    __half* valL  = (__half*)(S + OFF_VAL_L);
    __half* valtH = (__half*)(S + OFF_VALT_H);
    __half* valtL = (__half*)(S + OFF_VALT_L);
    __half* hf    = (__half*)(S + OFF_HF);
    __half* lat[3];
    for (int i = 0; i < 3; i++) lat[i] = (__half*)(S + OFF_LAT + i * W_LATP);
    float*  mlp32 = S + OFF_MLP32;
    float*  tmp32 = S + OFF_TMP32;
    __half* wtH   = (__half*)(S + OFF_WT_H);
    __half* wtL   = (__half*)(S + OFF_WT_L);

    const float WS = 1.0f / 16.0f;   // weight un-scale

    // launch idx: 0 encoder, 1 prep, 2 att_global, 3 k_gh  (ncu window -> GEMM)
    k_encoder<<<(BB * NF * CC / 2) / 256, 256>>>(x, en_w, en_b, hf);

    // ---- down attention (global, Nq=1024, Nk=4096) ----
    k_prep_whead<<<256, 256>>>(down_w, wtH, wtL);
    k_att_global<<<HH * NL, 256, (NF + 256) * sizeof(float)>>>(md_down, down_r, att, NL, NF);
    k_gh<<<dim3(BB * NF / 128, 4, 1), 128>>>(
        hf, wtH, wtL, valH, valL, 256, 0, 0,
        nullptr, nullptr, WS, 0, 2, NF);
    k_transp2<<<dim3(NF / 32, 8, HH), dim3(32, 8)>>>(valH, valL, valtH, valtL, NF);
    k_gh<<<dim3(NL / 128, 4, HH), 128>>>(
        att, valtH, valtL, lat[0], nullptr, NF,
        (size_t)NL * NF, (size_t)256 * NF,
        nullptr, nullptr, 1.0f, 1, 1, NL);

    // ---- two latent PiT blocks (masked attention, locality=30) ----
    int ih = 0, ip = 1, it = 2;
    for (int i = 0; i < 2; i++) {
        k_prep_whead<<<256, 256>>>(pa_w[i], wtH, wtL);
        k_gh<<<dim3(BB * NL / 128, 4, 1), 128>>>(
            lat[ih], wtH, wtL, valH, valL, 256, 0, 0,
            nullptr, nullptr, WS, 0, 2, NL);
        k_transp2<<<dim3(NL / 32, 8, HH), dim3(32, 8)>>>(valH, valL, valtH, valtL, NL);
        k_att_masked<<<HH * NL, 256>>>(md_p[i], pa_r[i], attp);
        k_gh<<<dim3(NL / 128, 4, HH), 128>>>(
            attp, valtH, valtL, lat[ip], nullptr, NL,
            (size_t)NL * NL, (size_t)256 * NL,
            nullptr, nullptr, 1.0f, 1, 1, NL);
        // mlp fc1 (gelu) -> lat[it]
        k_prep_wT<<<256, 256>>>(f1w[i], wtH, wtL);
        k_gh<<<dim3(BB * NL / 128, 4, 1), 128>>>(
            lat[ip], wtH, wtL, lat[it], nullptr, 256, 0, 0,
            f1b[i], nullptr, WS, 1, 0, 0);
        // mlp fc2 -> mlp32 (fp32, no act)
        k_prep_wT<<<256, 256>>>(f2w[i], wtH, wtL);
        k_gh<<<dim3(BB * NL / 128, 4, 1), 128>>>(
            lat[it], wtH, wtL, mlp32, nullptr, 256, 0, 0,
            f2b[i], nullptr, WS, 4, 0, 0);
        // h = gelu(mlp32 + hin@rw + rb) -> lat[it]
        k_prep_wT<<<256, 256>>>(rw[i], wtH, wtL);
        k_gh<<<dim3(BB * NL / 128, 4, 1), 128>>>(
            lat[ih], wtH, wtL, lat[it], nullptr, 256, 0, 0,
            rb[i], mlp32, WS, 3, 0, 0);
        int t = ih; ih = it; it = t;
    }

    // ---- up attention (global, Nq=4096, Nk=1024) ----
    k_prep_whead<<<256, 256>>>(up_w, wtH, wtL);
    k_gh<<<dim3(BB * NL / 128, 4, 1), 128>>>(
        lat[ih], wtH, wtL, valH, valL, 256, 0, 0,
        nullptr, nullptr, WS, 0, 2, NL);
    k_transp2<<<dim3(NL / 32, 8, HH), dim3(32, 8)>>>(valH, valL, valtH, valtL, NL);
    k_att_global<<<HH * NF, 256, (NL + 256) * sizeof(float)>>>(md_up, up_r, att, NF, NL);
    k_gh<<<dim3(NF / 128, 4, HH), 128>>>(
        att, valtH, valtL, hf, nullptr, NL,
        (size_t)NF * NL, (size_t)256 * NL,
        nullptr, nullptr, 1.0f, 1, 1, NF);

    // ---- decoder ----
    k_prep_wT<<<256, 256>>>(de1w, wtH, wtL);
    k_gh<<<dim3(BB * NF / 128, 4, 1), 128>>>(
        hf, wtH, wtL, tmp32, nullptr, 256, 0, 0,
        de1b, nullptr, WS, 5, 0, 0);   // gelu + fp32 store
    k_fc2<<<(BB * NF * 32) / 256, 256>>>(tmp32, de2w, de2b, (float*)d_out, BB * NF);
}